// round 1
// baseline (speedup 1.0000x reference)
#include <cuda_runtime.h>

// Problem constants
#define NB   4
#define NT   16
#define BTB  64            // NB*NT
#define NN   2000
#define DD   64
#define EE   32000
#define NEDG (EE + NN)     // edges + self loops = 34000
#define NDP  (NN * DD)     // 128000 floats per (b,t) slice
#define TOT  (BTB * NDP)   // 8,192,000 floats per activation buffer
#define MAXDEG 320

// ---------------- device scratch (no allocations allowed) ----------------
__device__ float g_bufA[TOT];          // 32.8 MB
__device__ float g_bufB[TOT];          // 32.8 MB
__device__ int   g_row[NN + 1];
__device__ int   g_col[NEDG];
__device__ float g_w[NEDG];
__device__ int   g_degi[NN];
__device__ float g_dinv[NN];
__device__ int   g_cursor[NN];
__device__ int   g_is64;
__device__ float g_pooled[BTB * DD];

__device__ __forceinline__ float fsilu(float x) {
    return x / (1.0f + __expf(-x));
}

// ---------------- 1) init degrees (self-loop = 1) + dtype detection ------
__global__ void k_init(const int* __restrict__ edges32) {
    int i = blockIdx.x * blockDim.x + threadIdx.x;
    if (i < NN) g_degi[i] = 1;
    if (i == 0) {
        // int64 little-endian: high 32-bit word of each element is 0 (values in [0,2000)).
        // For int32 data these words are random node ids; P(all 128 zero) ~ 0.
        int any = 0;
        #pragma unroll 1
        for (int j = 0; j < 128; j++) any |= edges32[2 * j + 1];
        g_is64 = (any == 0) ? 1 : 0;
    }
}

// ---------------- 2) degree histogram over dst ---------------------------
__global__ void k_deg(const void* __restrict__ edges) {
    int e = blockIdx.x * blockDim.x + threadIdx.x;
    if (e >= EE) return;
    int d;
    if (g_is64) d = (int)((const long long*)edges)[EE + e];
    else        d = ((const int*)edges)[EE + e];
    atomicAdd(&g_degi[d], 1);
}

// ---------------- 3) exclusive scan -> row_start, dinv, cursors ----------
__global__ void k_scan() {
    __shared__ int chunk[256];
    int t = threadIdx.x;
    int base = t * 8;
    int vals[8];
    int s = 0;
    #pragma unroll
    for (int q = 0; q < 8; q++) {
        int idx = base + q;
        int v = (idx < NN) ? g_degi[idx] : 0;
        vals[q] = v;
        s += v;
    }
    chunk[t] = s;
    __syncthreads();
    for (int off = 1; off < 256; off <<= 1) {
        int v = (t >= off) ? chunk[t - off] : 0;
        __syncthreads();
        chunk[t] += v;
        __syncthreads();
    }
    int run = chunk[t] - s;  // exclusive prefix of this chunk
    #pragma unroll
    for (int q = 0; q < 8; q++) {
        int idx = base + q;
        if (idx <= NN) g_row[idx] = run;
        if (idx < NN) {
            g_cursor[idx] = run;
            g_dinv[idx] = rsqrtf((float)vals[q]);
        }
        run += vals[q];
    }
}

// ---------------- 4) fill CSR (edges + self loops) -----------------------
__global__ void k_fill(const void* __restrict__ edges) {
    int e = blockIdx.x * blockDim.x + threadIdx.x;
    if (e >= NEDG) return;
    int s, d;
    if (e < EE) {
        if (g_is64) {
            s = (int)((const long long*)edges)[e];
            d = (int)((const long long*)edges)[EE + e];
        } else {
            s = ((const int*)edges)[e];
            d = ((const int*)edges)[EE + e];
        }
    } else {
        s = d = e - EE;   // self loop
    }
    int pos = atomicAdd(&g_cursor[d], 1);
    g_col[pos] = s;
    g_w[pos]   = g_dinv[s] * g_dinv[d];
}

// ---------------- 5) per-row sort by col: deterministic sum order --------
__global__ void k_sort() {
    int n = blockIdx.x * blockDim.x + threadIdx.x;
    if (n >= NN) return;
    int r0 = g_row[n], r1 = g_row[n + 1];
    for (int i = r0 + 1; i < r1; i++) {
        int c = g_col[i];
        float w = g_w[i];
        int j = i - 1;
        while (j >= r0 && g_col[j] > c) {
            g_col[j + 1] = g_col[j];
            g_w[j + 1]   = g_w[j];
            j--;
        }
        g_col[j + 1] = c;
        g_w[j + 1]   = w;
    }
}

// ---------------- 6) sparse aggregation: bufB = A * in -------------------
// One block per dst node. CSR row cached in shared; 16 groups of 16 threads,
// each group handles one (bt) slice at a time with float4 (16B/thread) loads.
__global__ void k_agg(const float* __restrict__ xin, int use_x) {
    const float* __restrict__ in = use_x ? xin : g_bufA;
    int n = blockIdx.x;
    int r0 = g_row[n];
    int deg = g_row[n + 1] - r0;
    __shared__ int   scol[MAXDEG];
    __shared__ float swgt[MAXDEG];
    int m = (deg < MAXDEG) ? deg : MAXDEG;
    for (int j = threadIdx.x; j < m; j += 256) {
        scol[j] = g_col[r0 + j] << 6;   // node offset in floats
        swgt[j] = g_w[r0 + j];
    }
    __syncthreads();

    int lane = (threadIdx.x & 15) << 2;   // d offset (float4)
    int grp  = threadIdx.x >> 4;          // 0..15
    int outbase = (n << 6) + lane;

    for (int bt = grp; bt < BTB; bt += 16) {
        const float* bp = in + bt * NDP;
        float4 acc = make_float4(0.f, 0.f, 0.f, 0.f);
        int j = 0;
        #pragma unroll 4
        for (; j < m; j++) {
            float w = swgt[j];
            float4 v = *(const float4*)(bp + scol[j] + lane);
            acc.x += w * v.x; acc.y += w * v.y;
            acc.z += w * v.z; acc.w += w * v.w;
        }
        for (int jj = MAXDEG; jj < deg; jj++) {   // overflow fallback (rare/never)
            float w = g_w[r0 + jj];
            float4 v = *(const float4*)(bp + (g_col[r0 + jj] << 6) + lane);
            acc.x += w * v.x; acc.y += w * v.y;
            acc.z += w * v.z; acc.w += w * v.w;
        }
        *(float4*)(g_bufB + bt * NDP + outbase) = acc;
    }
}

// ---------------- 7) dense GEMM + bias + SiLU: bufA = silu(bufB@W + b) ---
// 64 rows x 64 cols per block; 16x16 threads, 4x4 micro-tile.
__global__ void k_gemm(const float* __restrict__ W, const float* __restrict__ bias) {
    __shared__ __align__(16) float Xs[64 * 65];
    __shared__ __align__(16) float Ws[64 * 64];
    __shared__ float bs[64];
    int row0 = blockIdx.x << 6;
    int tid = threadIdx.x;
    for (int idx = tid; idx < 4096; idx += 256) {
        int r = idx >> 6, k = idx & 63;
        Xs[r * 65 + k] = g_bufB[(row0 << 6) + idx];
        Ws[idx] = W[idx];
    }
    if (tid < 64) bs[tid] = bias[tid];
    __syncthreads();

    int tx = tid & 15, ty = tid >> 4;
    float acc[4][4];
    #pragma unroll
    for (int i = 0; i < 4; i++)
        #pragma unroll
        for (int j = 0; j < 4; j++) acc[i][j] = 0.f;

    #pragma unroll
    for (int k = 0; k < 64; k++) {
        float4 wv = *(const float4*)&Ws[k * 64 + (tx << 2)];
        #pragma unroll
        for (int i = 0; i < 4; i++) {
            float xv = Xs[(ty * 4 + i) * 65 + k];
            acc[i][0] += xv * wv.x;
            acc[i][1] += xv * wv.y;
            acc[i][2] += xv * wv.z;
            acc[i][3] += xv * wv.w;
        }
    }

    float4 bc = *(const float4*)&bs[tx << 2];
    #pragma unroll
    for (int i = 0; i < 4; i++) {
        int r = row0 + ty * 4 + i;
        float4 o;
        o.x = fsilu(acc[i][0] + bc.x);
        o.y = fsilu(acc[i][1] + bc.y);
        o.z = fsilu(acc[i][2] + bc.z);
        o.w = fsilu(acc[i][3] + bc.w);
        *(float4*)&g_bufA[(r << 6) + (tx << 2)] = o;
    }
}

// ---------------- 8) mean pool over nodes --------------------------------
__global__ void k_pool() {
    __shared__ float sp[4][64];
    int bt = blockIdx.x;
    int d = threadIdx.x & 63, part = threadIdx.x >> 6;
    float a0 = 0.f, a1 = 0.f, a2 = 0.f, a3 = 0.f;
    const float* bp = g_bufA + bt * NDP + d;
    for (int n0 = part; n0 < NN; n0 += 16) {       // NN = 125*16, exact coverage
        a0 += bp[(n0      ) << 6];
        a1 += bp[(n0 +  4 ) << 6];
        a2 += bp[(n0 +  8 ) << 6];
        a3 += bp[(n0 + 12 ) << 6];
    }
    sp[part][d] = a0 + a1 + a2 + a3;
    __syncthreads();
    if (part == 0)
        g_pooled[bt * 64 + d] =
            (sp[0][d] + sp[1][d] + sp[2][d] + sp[3][d]) * (1.0f / NN);
}

// ---------------- 9) LSTM (T=16, batch 4) + MLP head, single block -------
__global__ void k_lstm(const float* __restrict__ Wih, const float* __restrict__ Whh,
                       const float* __restrict__ bih, const float* __restrict__ bhh,
                       const float* __restrict__ Wp1, const float* __restrict__ bp1,
                       const float* __restrict__ Wp2, const float* __restrict__ bp2,
                       const float* __restrict__ Wp3, const float* __restrict__ bp3,
                       float* __restrict__ out) {
    __shared__ float sh[NB][DD], sc[NB][DD], sxt[NB][DD];
    __shared__ float sg[NB][4 * DD];
    __shared__ float sz1[NB][2 * DD], sz2[NB][DD];
    int tid = threadIdx.x;
    {
        int b = tid >> 6, d = tid & 63;
        sh[b][d] = 0.f;
        sc[b][d] = 0.f;
    }
    // thread tid owns gate row g = tid; cache its weight rows in registers
    float wi[64], wh[64];
    #pragma unroll
    for (int k = 0; k < 64; k++) {
        wi[k] = Wih[tid * 64 + k];
        wh[k] = Whh[tid * 64 + k];
    }
    float bb = bih[tid] + bhh[tid];
    __syncthreads();

    for (int t = 0; t < NT; t++) {
        {
            int b = tid >> 6, d = tid & 63;
            sxt[b][d] = g_pooled[(b * NT + t) * 64 + d];
        }
        __syncthreads();
        float a0 = bb, a1 = bb, a2 = bb, a3 = bb;
        #pragma unroll
        for (int k = 0; k < 64; k++) {
            float w1 = wi[k], w2 = wh[k];
            a0 += sxt[0][k] * w1 + sh[0][k] * w2;
            a1 += sxt[1][k] * w1 + sh[1][k] * w2;
            a2 += sxt[2][k] * w1 + sh[2][k] * w2;
            a3 += sxt[3][k] * w1 + sh[3][k] * w2;
        }
        sg[0][tid] = a0; sg[1][tid] = a1; sg[2][tid] = a2; sg[3][tid] = a3;
        __syncthreads();
        {
            int b = tid >> 6, d = tid & 63;
            float ig = 1.f / (1.f + expf(-sg[b][d]));
            float fg = 1.f / (1.f + expf(-sg[b][64 + d]));
            float gg = tanhf(sg[b][128 + d]);
            float og = 1.f / (1.f + expf(-sg[b][192 + d]));
            float c = fg * sc[b][d] + ig * gg;
            sc[b][d] = c;
            sh[b][d] = og * tanhf(c);
        }
        __syncthreads();
    }

    // head: 64 -> 128 (silu) -> 64 (silu) -> 8
    for (int jj = tid; jj < NB * 128; jj += 256) {
        int b = jj >> 7, j = jj & 127;
        float acc = bp1[j];
        #pragma unroll
        for (int k = 0; k < 64; k++) acc += sh[b][k] * Wp1[k * 128 + j];
        sz1[b][j] = acc / (1.f + expf(-acc));
    }
    __syncthreads();
    {
        int b = tid >> 6, j2 = tid & 63;
        float acc = bp2[j2];
        #pragma unroll
        for (int j = 0; j < 128; j++) acc += sz1[b][j] * Wp2[j * 64 + j2];
        sz2[b][j2] = acc / (1.f + expf(-acc));
    }
    __syncthreads();
    if (tid < 32) {
        int b = tid >> 3, o = tid & 7;
        float acc = bp3[o];
        #pragma unroll
        for (int j2 = 0; j2 < 64; j2++) acc += sz2[b][j2] * Wp3[j2 * 8 + o];
        out[b * 8 + o] = acc;
    }
}

// ---------------- launch --------------------------------------------------
extern "C" void kernel_launch(void* const* d_in, const int* in_sizes, int n_in,
                              void* d_out, int out_size) {
    const float* x   = (const float*)d_in[0];
    const void*  ei  = d_in[1];
    const float* W1  = (const float*)d_in[2];
    const float* b1  = (const float*)d_in[3];
    const float* W2  = (const float*)d_in[4];
    const float* b2  = (const float*)d_in[5];
    const float* W3  = (const float*)d_in[6];
    const float* b3  = (const float*)d_in[7];
    const float* Wih = (const float*)d_in[8];
    const float* Whh = (const float*)d_in[9];
    const float* bih = (const float*)d_in[10];
    const float* bhh = (const float*)d_in[11];
    const float* Wp1 = (const float*)d_in[12];
    const float* bp1 = (const float*)d_in[13];
    const float* Wp2 = (const float*)d_in[14];
    const float* bp2 = (const float*)d_in[15];
    const float* Wp3 = (const float*)d_in[16];
    const float* bp3 = (const float*)d_in[17];
    float* out = (float*)d_out;

    // graph preprocessing (rebuilt every launch; deterministic end state)
    k_init<<<(NN + 255) / 256, 256>>>((const int*)ei);
    k_deg<<<(EE + 255) / 256, 256>>>(ei);
    k_scan<<<1, 256>>>();
    k_fill<<<(NEDG + 255) / 256, 256>>>(ei);
    k_sort<<<(NN + 127) / 128, 128>>>();

    // layer 1: bufB = A*x ; bufA = silu(bufB@W1 + b1)
    k_agg<<<NN, 256>>>(x, 1);
    k_gemm<<<(BTB * NN) / 64, 256>>>(W1, b1);
    // layer 2
    k_agg<<<NN, 256>>>(x, 0);
    k_gemm<<<(BTB * NN) / 64, 256>>>(W2, b2);
    // layer 3
    k_agg<<<NN, 256>>>(x, 0);
    k_gemm<<<(BTB * NN) / 64, 256>>>(W3, b3);

    k_pool<<<BTB, 256>>>();
    k_lstm<<<1, 256>>>(Wih, Whh, bih, bhh, Wp1, bp1, Wp2, bp2, Wp3, bp3, out);
}

// round 2
// speedup vs baseline: 1.4014x; 1.4014x over previous
#include <cuda_runtime.h>
#include <cuda_fp16.h>

// Problem constants
#define NB   4
#define NT   16
#define BTB  64            // NB*NT
#define NN   2000
#define DD   64
#define EE   32000
#define NEDG (EE + NN)     // edges + self loops = 34000
#define NDP  (NN * DD)     // elements per (b,t) slice
#define TOT  (BTB * NDP)   // 8,192,000 elements per activation buffer
#define MAXDEG 320

// ---------------- device scratch (no allocations allowed) ----------------
__device__ __half g_h0[TOT];           // 16.4 MB ping
__device__ __half g_h1[TOT];           // 16.4 MB pong
__device__ int    g_row[NN + 1];
__device__ int2   g_edge[NEDG];        // (col<<6, weight bits), row-sorted
__device__ int    g_degi[NN];          // zero-init; k_scan resets to 0 each launch
__device__ float  g_dinv[NN];
__device__ int    g_cursor[NN];
__device__ float  g_pooled[BTB * DD];

__device__ __forceinline__ float fsilu(float x) {
    return x / (1.0f + __expf(-x));
}

// packed f32x2 helpers (ptxas never emits FFMA2 from C++)
__device__ __forceinline__ unsigned long long packf2(float lo, float hi) {
    unsigned long long d;
    asm("mov.b64 %0, {%1, %2};" : "=l"(d) : "f"(lo), "f"(hi));
    return d;
}
__device__ __forceinline__ unsigned long long ffma2(unsigned long long a,
                                                    unsigned long long b,
                                                    unsigned long long c) {
    unsigned long long d;
    asm("fma.rn.f32x2 %0, %1, %2, %3;" : "=l"(d) : "l"(a), "l"(b), "l"(c));
    return d;
}
__device__ __forceinline__ float2 unpack2(unsigned long long u) {
    float2 f;
    asm("mov.b64 {%0, %1}, %2;" : "=f"(f.x), "=f"(f.y) : "l"(u));
    return f;
}

// edge_index dtype detection (int64 LE: high words of values <2000 are all 0)
__device__ __forceinline__ int detect64(const int* e32) {
    int any = 0;
    #pragma unroll 1
    for (int j = 0; j < 128; j++) any |= e32[2 * j + 1];
    return (any == 0) ? 1 : 0;
}

// ---------------- 0) convert x (fp32) -> g_h0 (fp16) ---------------------
__global__ void k_cvt(const float* __restrict__ x) {
    int i = blockIdx.x * blockDim.x + threadIdx.x;
    if (i >= TOT / 4) return;
    float4 v = ((const float4*)x)[i];
    __half2 h0 = __floats2half2_rn(v.x, v.y);
    __half2 h1 = __floats2half2_rn(v.z, v.w);
    uint2 o;
    o.x = *(unsigned*)&h0;
    o.y = *(unsigned*)&h1;
    ((uint2*)g_h0)[i] = o;
}

// ---------------- 1) degree histogram over dst (g_degi starts zeroed) ----
__global__ void k_deg(const void* __restrict__ edges) {
    __shared__ int s64;
    if (threadIdx.x == 0) s64 = detect64((const int*)edges);
    __syncthreads();
    int e = blockIdx.x * blockDim.x + threadIdx.x;
    if (e >= EE) return;
    int d = s64 ? (int)((const long long*)edges)[EE + e]
                : ((const int*)edges)[EE + e];
    atomicAdd(&g_degi[d], 1);
}

// ---------------- 2) scan (+1 self loop), dinv, cursors, reset degi ------
__global__ void k_scan() {
    __shared__ int chunk[256];
    int t = threadIdx.x;
    int base = t * 8;
    int vals[8];
    int s = 0;
    #pragma unroll
    for (int q = 0; q < 8; q++) {
        int idx = base + q;
        int v = 0;
        if (idx < NN) {
            v = g_degi[idx] + 1;   // + self loop
            g_degi[idx] = 0;       // reset for next launch (determinism)
        }
        vals[q] = v;
        s += v;
    }
    chunk[t] = s;
    __syncthreads();
    for (int off = 1; off < 256; off <<= 1) {
        int v = (t >= off) ? chunk[t - off] : 0;
        __syncthreads();
        chunk[t] += v;
        __syncthreads();
    }
    int run = chunk[t] - s;
    #pragma unroll
    for (int q = 0; q < 8; q++) {
        int idx = base + q;
        if (idx <= NN) g_row[idx] = run;
        if (idx < NN) {
            g_cursor[idx] = run;
            g_dinv[idx] = rsqrtf((float)vals[q]);
        }
        run += vals[q];
    }
}

// ---------------- 3) fill CSR (edges + self loops) -----------------------
__global__ void k_fill(const void* __restrict__ edges) {
    __shared__ int s64;
    if (threadIdx.x == 0) s64 = detect64((const int*)edges);
    __syncthreads();
    int e = blockIdx.x * blockDim.x + threadIdx.x;
    if (e >= NEDG) return;
    int s, d;
    if (e < EE) {
        if (s64) {
            s = (int)((const long long*)edges)[e];
            d = (int)((const long long*)edges)[EE + e];
        } else {
            s = ((const int*)edges)[e];
            d = ((const int*)edges)[EE + e];
        }
    } else {
        s = d = e - EE;   // self loop
    }
    int pos = atomicAdd(&g_cursor[d], 1);
    g_edge[pos] = make_int2(s << 6, __float_as_int(g_dinv[s] * g_dinv[d]));
}

// ---------------- 4) per-row sort by col: deterministic sum order --------
__global__ void k_sort() {
    int n = blockIdx.x * blockDim.x + threadIdx.x;
    if (n >= NN) return;
    int r0 = g_row[n], r1 = g_row[n + 1];
    for (int i = r0 + 1; i < r1; i++) {
        int2 key = g_edge[i];
        int j = i - 1;
        while (j >= r0 && g_edge[j].x > key.x) {
            g_edge[j + 1] = g_edge[j];
            j--;
        }
        g_edge[j + 1] = key;
    }
}

// ---------------- 5) fused aggregate + GEMM + bias + SiLU ----------------
__global__ void k_aggemm(const float* __restrict__ W,
                         const float* __restrict__ bias, int dir) {
    __shared__ __align__(16) float Ws[64 * 64];   // 16 KB
    __shared__ __align__(16) float bs[64];
    __shared__ __align__(16) float sagg[64][64];  // 16 KB
    __shared__ int2 sedge[MAXDEG];

    const __half* __restrict__ in  = dir ? g_h1 : g_h0;
    __half* __restrict__       out = dir ? g_h0 : g_h1;

    int n = blockIdx.x;
    int r0 = g_row[n];
    int deg = g_row[n + 1] - r0;
    int m = (deg < MAXDEG) ? deg : MAXDEG;
    int tid = threadIdx.x;

    for (int idx = tid; idx < 4096; idx += 256) Ws[idx] = W[idx];
    if (tid < 64) bs[tid] = bias[tid];
    for (int j = tid; j < m; j += 256) sedge[j] = g_edge[r0 + j];
    __syncthreads();

    int lane  = tid & 15;
    int grp   = tid >> 4;
    int lane4 = lane << 2;

    const __half* bp0 = in + (grp     ) * NDP + lane4;
    const __half* bp1 = in + (grp + 16) * NDP + lane4;
    const __half* bp2 = in + (grp + 32) * NDP + lane4;
    const __half* bp3 = in + (grp + 48) * NDP + lane4;

    unsigned long long a00 = 0, a01 = 0, a10 = 0, a11 = 0;
    unsigned long long a20 = 0, a21 = 0, a30 = 0, a31 = 0;

    #pragma unroll 2
    for (int j = 0; j < m; j++) {
        int2 e = sedge[j];
        float w = __int_as_float(e.y);
        unsigned long long ww = packf2(w, w);
        int off = e.x;
        uint2 hv;
        float2 f0, f1;
        hv = *(const uint2*)(bp0 + off);
        f0 = __half22float2(*(__half2*)&hv.x); f1 = __half22float2(*(__half2*)&hv.y);
        a00 = ffma2(ww, packf2(f0.x, f0.y), a00); a01 = ffma2(ww, packf2(f1.x, f1.y), a01);
        hv = *(const uint2*)(bp1 + off);
        f0 = __half22float2(*(__half2*)&hv.x); f1 = __half22float2(*(__half2*)&hv.y);
        a10 = ffma2(ww, packf2(f0.x, f0.y), a10); a11 = ffma2(ww, packf2(f1.x, f1.y), a11);
        hv = *(const uint2*)(bp2 + off);
        f0 = __half22float2(*(__half2*)&hv.x); f1 = __half22float2(*(__half2*)&hv.y);
        a20 = ffma2(ww, packf2(f0.x, f0.y), a20); a21 = ffma2(ww, packf2(f1.x, f1.y), a21);
        hv = *(const uint2*)(bp3 + off);
        f0 = __half22float2(*(__half2*)&hv.x); f1 = __half22float2(*(__half2*)&hv.y);
        a30 = ffma2(ww, packf2(f0.x, f0.y), a30); a31 = ffma2(ww, packf2(f1.x, f1.y), a31);
    }
    for (int j = MAXDEG; j < deg; j++) {   // overflow fallback (never expected)
        int2 e = g_edge[r0 + j];
        float w = __int_as_float(e.y);
        unsigned long long ww = packf2(w, w);
        int off = e.x;
        uint2 hv;
        float2 f0, f1;
        hv = *(const uint2*)(bp0 + off);
        f0 = __half22float2(*(__half2*)&hv.x); f1 = __half22float2(*(__half2*)&hv.y);
        a00 = ffma2(ww, packf2(f0.x, f0.y), a00); a01 = ffma2(ww, packf2(f1.x, f1.y), a01);
        hv = *(const uint2*)(bp1 + off);
        f0 = __half22float2(*(__half2*)&hv.x); f1 = __half22float2(*(__half2*)&hv.y);
        a10 = ffma2(ww, packf2(f0.x, f0.y), a10); a11 = ffma2(ww, packf2(f1.x, f1.y), a11);
        hv = *(const uint2*)(bp2 + off);
        f0 = __half22float2(*(__half2*)&hv.x); f1 = __half22float2(*(__half2*)&hv.y);
        a20 = ffma2(ww, packf2(f0.x, f0.y), a20); a21 = ffma2(ww, packf2(f1.x, f1.y), a21);
        hv = *(const uint2*)(bp3 + off);
        f0 = __half22float2(*(__half2*)&hv.x); f1 = __half22float2(*(__half2*)&hv.y);
        a30 = ffma2(ww, packf2(f0.x, f0.y), a30); a31 = ffma2(ww, packf2(f1.x, f1.y), a31);
    }

    {
        float2 lo, hi;
        lo = unpack2(a00); hi = unpack2(a01);
        *(float4*)&sagg[grp     ][lane4] = make_float4(lo.x, lo.y, hi.x, hi.y);
        lo = unpack2(a10); hi = unpack2(a11);
        *(float4*)&sagg[grp + 16][lane4] = make_float4(lo.x, lo.y, hi.x, hi.y);
        lo = unpack2(a20); hi = unpack2(a21);
        *(float4*)&sagg[grp + 32][lane4] = make_float4(lo.x, lo.y, hi.x, hi.y);
        lo = unpack2(a30); hi = unpack2(a31);
        *(float4*)&sagg[grp + 48][lane4] = make_float4(lo.x, lo.y, hi.x, hi.y);
    }
    __syncwarp();

    const ulonglong2* Wp = (const ulonglong2*)Ws;
    ulonglong2 bb = ((const ulonglong2*)bs)[lane];
    unsigned long long o00 = bb.x, o01 = bb.y, o10 = bb.x, o11 = bb.y;
    unsigned long long o20 = bb.x, o21 = bb.y, o30 = bb.x, o31 = bb.y;

    #pragma unroll 16
    for (int k = 0; k < 64; k++) {
        ulonglong2 wv = Wp[k * 16 + lane];
        unsigned long long aa;
        float a;
        a = sagg[grp     ][k]; aa = packf2(a, a);
        o00 = ffma2(aa, wv.x, o00); o01 = ffma2(aa, wv.y, o01);
        a = sagg[grp + 16][k]; aa = packf2(a, a);
        o10 = ffma2(aa, wv.x, o10); o11 = ffma2(aa, wv.y, o11);
        a = sagg[grp + 32][k]; aa = packf2(a, a);
        o20 = ffma2(aa, wv.x, o20); o21 = ffma2(aa, wv.y, o21);
        a = sagg[grp + 48][k]; aa = packf2(a, a);
        o30 = ffma2(aa, wv.x, o30); o31 = ffma2(aa, wv.y, o31);
    }

    int obase = (n << 6) + lane4;
    {
        float2 f0 = unpack2(o00), f1 = unpack2(o01);
        __half2 h0 = __floats2half2_rn(fsilu(f0.x), fsilu(f0.y));
        __half2 h1 = __floats2half2_rn(fsilu(f1.x), fsilu(f1.y));
        uint2 v; v.x = *(unsigned*)&h0; v.y = *(unsigned*)&h1;
        *(uint2*)(out + (grp     ) * NDP + obase) = v;
    }
    {
        float2 f0 = unpack2(o10), f1 = unpack2(o11);
        __half2 h0 = __floats2half2_rn(fsilu(f0.x), fsilu(f0.y));
        __half2 h1 = __floats2half2_rn(fsilu(f1.x), fsilu(f1.y));
        uint2 v; v.x = *(unsigned*)&h0; v.y = *(unsigned*)&h1;
        *(uint2*)(out + (grp + 16) * NDP + obase) = v;
    }
    {
        float2 f0 = unpack2(o20), f1 = unpack2(o21);
        __half2 h0 = __floats2half2_rn(fsilu(f0.x), fsilu(f0.y));
        __half2 h1 = __floats2half2_rn(fsilu(f1.x), fsilu(f1.y));
        uint2 v; v.x = *(unsigned*)&h0; v.y = *(unsigned*)&h1;
        *(uint2*)(out + (grp + 32) * NDP + obase) = v;
    }
    {
        float2 f0 = unpack2(o30), f1 = unpack2(o31);
        __half2 h0 = __floats2half2_rn(fsilu(f0.x), fsilu(f0.y));
        __half2 h1 = __floats2half2_rn(fsilu(f1.x), fsilu(f1.y));
        uint2 v; v.x = *(unsigned*)&h0; v.y = *(unsigned*)&h1;
        *(uint2*)(out + (grp + 48) * NDP + obase) = v;
    }
}

// ---------------- 6) mean pool over nodes (reads g_h1, fp16) -------------
__global__ void k_pool() {
    __shared__ float2 sp[16][32];
    int bt = blockIdx.x;
    int d2 = threadIdx.x & 31;
    int part = threadIdx.x >> 5;   // 16 partials
    const __half2* bp = (const __half2*)(g_h1 + bt * NDP) + d2;
    float2 a = make_float2(0.f, 0.f);
    for (int n0 = part; n0 < NN; n0 += 16) {
        float2 v = __half22float2(bp[n0 * 32]);
        a.x += v.x;
        a.y += v.y;
    }
    sp[part][d2] = a;
    __syncthreads();
    if (part == 0) {
        float2 t = sp[0][d2];
        #pragma unroll
        for (int i = 1; i < 16; i++) {
            float2 v = sp[i][d2];
            t.x += v.x;
            t.y += v.y;
        }
        g_pooled[bt * 64 + 2 * d2]     = t.x * (1.0f / NN);
        g_pooled[bt * 64 + 2 * d2 + 1] = t.y * (1.0f / NN);
    }
}

// ---------------- 7) LSTM (T=16, batch 4) + MLP head, single block -------
__global__ void k_lstm(const float* __restrict__ Wih, const float* __restrict__ Whh,
                       const float* __restrict__ bih, const float* __restrict__ bhh,
                       const float* __restrict__ Wp1, const float* __restrict__ bp1,
                       const float* __restrict__ Wp2, const float* __restrict__ bp2,
                       const float* __restrict__ Wp3, const float* __restrict__ bp3,
                       float* __restrict__ out) {
    __shared__ float sh[NB][DD], sc[NB][DD], sxt[NB][DD];
    __shared__ float sg[NB][4 * DD];
    __shared__ float sz1[NB][2 * DD], sz2[NB][DD];
    int tid = threadIdx.x;
    {
        int b = tid >> 6, d = tid & 63;
        sh[b][d] = 0.f;
        sc[b][d] = 0.f;
    }
    float wi[64], wh[64];
    #pragma unroll
    for (int k = 0; k < 64; k++) {
        wi[k] = Wih[tid * 64 + k];
        wh[k] = Whh[tid * 64 + k];
    }
    float bb = bih[tid] + bhh[tid];
    __syncthreads();

    for (int t = 0; t < NT; t++) {
        {
            int b = tid >> 6, d = tid & 63;
            sxt[b][d] = g_pooled[(b * NT + t) * 64 + d];
        }
        __syncthreads();
        float a0 = bb, a1 = bb, a2 = bb, a3 = bb;
        #pragma unroll
        for (int k = 0; k < 64; k++) {
            float w1 = wi[k], w2 = wh[k];
            a0 += sxt[0][k] * w1 + sh[0][k] * w2;
            a1 += sxt[1][k] * w1 + sh[1][k] * w2;
            a2 += sxt[2][k] * w1 + sh[2][k] * w2;
            a3 += sxt[3][k] * w1 + sh[3][k] * w2;
        }
        sg[0][tid] = a0; sg[1][tid] = a1; sg[2][tid] = a2; sg[3][tid] = a3;
        __syncthreads();
        {
            int b = tid >> 6, d = tid & 63;
            float ig = 1.f / (1.f + expf(-sg[b][d]));
            float fg = 1.f / (1.f + expf(-sg[b][64 + d]));
            float gg = tanhf(sg[b][128 + d]);
            float og = 1.f / (1.f + expf(-sg[b][192 + d]));
            float c = fg * sc[b][d] + ig * gg;
            sc[b][d] = c;
            sh[b][d] = og * tanhf(c);
        }
        __syncthreads();
    }

    for (int jj = tid; jj < NB * 128; jj += 256) {
        int b = jj >> 7, j = jj & 127;
        float acc = bp1[j];
        #pragma unroll
        for (int k = 0; k < 64; k++) acc += sh[b][k] * Wp1[k * 128 + j];
        sz1[b][j] = acc / (1.f + expf(-acc));
    }
    __syncthreads();
    {
        int b = tid >> 6, j2 = tid & 63;
        float acc = bp2[j2];
        #pragma unroll
        for (int j = 0; j < 128; j++) acc += sz1[b][j] * Wp2[j * 64 + j2];
        sz2[b][j2] = acc / (1.f + expf(-acc));
    }
    __syncthreads();
    if (tid < 32) {
        int b = tid >> 3, o = tid & 7;
        float acc = bp3[o];
        #pragma unroll
        for (int j2 = 0; j2 < 64; j2++) acc += sz2[b][j2] * Wp3[j2 * 8 + o];
        out[b * 8 + o] = acc;
    }
}

// ---------------- launch --------------------------------------------------
extern "C" void kernel_launch(void* const* d_in, const int* in_sizes, int n_in,
                              void* d_out, int out_size) {
    const float* x   = (const float*)d_in[0];
    const void*  ei  = d_in[1];
    const float* W1  = (const float*)d_in[2];
    const float* b1  = (const float*)d_in[3];
    const float* W2  = (const float*)d_in[4];
    const float* b2  = (const float*)d_in[5];
    const float* W3  = (const float*)d_in[6];
    const float* b3  = (const float*)d_in[7];
    const float* Wih = (const float*)d_in[8];
    const float* Whh = (const float*)d_in[9];
    const float* bih = (const float*)d_in[10];
    const float* bhh = (const float*)d_in[11];
    const float* Wp1 = (const float*)d_in[12];
    const float* bp1 = (const float*)d_in[13];
    const float* Wp2 = (const float*)d_in[14];
    const float* bp2 = (const float*)d_in[15];
    const float* Wp3 = (const float*)d_in[16];
    const float* bp3 = (const float*)d_in[17];
    float* out = (float*)d_out;

    k_cvt<<<TOT / 4 / 256, 256>>>(x);
    k_deg<<<(EE + 255) / 256, 256>>>(ei);
    k_scan<<<1, 256>>>();
    k_fill<<<(NEDG + 255) / 256, 256>>>(ei);
    k_sort<<<(NN + 127) / 128, 128>>>();

    k_aggemm<<<NN, 256>>>(W1, b1, 0);   // h0 -> h1
    k_aggemm<<<NN, 256>>>(W2, b2, 1);   // h1 -> h0
    k_aggemm<<<NN, 256>>>(W3, b3, 0);   // h0 -> h1

    k_pool<<<BTB, 512>>>();
    k_lstm<<<1, 256>>>(Wih, Whh, bih, bhh, Wp1, bp1, Wp2, bp2, Wp3, bp3, out);
}

// round 3
// speedup vs baseline: 1.9706x; 1.4062x over previous
#include <cuda_runtime.h>
#include <cuda_fp16.h>

// Problem constants
#define NB   4
#define NT   16
#define BTB  64            // NB*NT
#define NN   2000
#define DD   64
#define EE   32000
#define NEDG (EE + NN)     // edges + self loops = 34000
#define NDP  (NN * DD)     // elements per (b,t) slice
#define TOT  (BTB * NDP)   // 8,192,000 elements per activation buffer
#define MAXDEG 320
#define SORT_BUF 4000

// ---------------- device scratch (no allocations allowed) ----------------
__device__ __half g_h0[TOT];           // 16.4 MB ping
__device__ __half g_h1[TOT];           // 16.4 MB pong
__device__ int    g_row[NN + 1];
__device__ int2   g_edge[NEDG];        // (col<<6, half2(w,w) bits), row-sorted
__device__ int    g_degi[NN];          // zero-init; k_scan resets each launch
__device__ float  g_dinv[NN];
__device__ int    g_cursor[NN];
__device__ int    g_is64;
__device__ float  g_pooled[BTB * DD];

__device__ __forceinline__ float fsilu(float x) {
    return x / (1.0f + __expf(-x));
}
__device__ __forceinline__ __half2 asH2(unsigned u) { return *(__half2*)&u; }

// ---------------- 0a) edge dtype detection (one warp, once) --------------
__global__ void k_detect(const int* __restrict__ e32) {
    int t = threadIdx.x;
    int any = 0;
    for (int j = t; j < 128; j += 32) any |= e32[2 * j + 1];
    any = __reduce_or_sync(0xffffffffu, any);
    if (t == 0) g_is64 = (any == 0) ? 1 : 0;   // all-zero high words => int64
}

// ---------------- 0b) convert x (fp32) -> g_h0 (fp16) --------------------
__global__ void k_cvt(const float* __restrict__ x) {
    int i = blockIdx.x * blockDim.x + threadIdx.x;
    if (i >= TOT / 4) return;
    float4 v = ((const float4*)x)[i];
    __half2 h0 = __floats2half2_rn(v.x, v.y);
    __half2 h1 = __floats2half2_rn(v.z, v.w);
    uint2 o;
    o.x = *(unsigned*)&h0;
    o.y = *(unsigned*)&h1;
    ((uint2*)g_h0)[i] = o;
}

// ---------------- 1) degree histogram over dst ---------------------------
__global__ void k_deg(const void* __restrict__ edges) {
    int e = blockIdx.x * blockDim.x + threadIdx.x;
    if (e >= EE) return;
    int d = g_is64 ? (int)((const long long*)edges)[EE + e]
                   : ((const int*)edges)[EE + e];
    atomicAdd(&g_degi[d], 1);
}

// ---------------- 2) scan (+1 self loop), dinv, cursors, reset degi ------
__global__ void k_scan() {
    __shared__ int chunk[256];
    int t = threadIdx.x;
    int base = t * 8;
    int vals[8];
    int s = 0;
    #pragma unroll
    for (int q = 0; q < 8; q++) {
        int idx = base + q;
        int v = 0;
        if (idx < NN) {
            v = g_degi[idx] + 1;   // + self loop
            g_degi[idx] = 0;       // reset for next launch
        }
        vals[q] = v;
        s += v;
    }
    chunk[t] = s;
    __syncthreads();
    for (int off = 1; off < 256; off <<= 1) {
        int v = (t >= off) ? chunk[t - off] : 0;
        __syncthreads();
        chunk[t] += v;
        __syncthreads();
    }
    int run = chunk[t] - s;
    #pragma unroll
    for (int q = 0; q < 8; q++) {
        int idx = base + q;
        if (idx <= NN) g_row[idx] = run;
        if (idx < NN) {
            g_cursor[idx] = run;
            g_dinv[idx] = rsqrtf((float)vals[q]);
        }
        run += vals[q];
    }
}

// ---------------- 3) fill CSR (edges + self loops), weight as half2 ------
__global__ void k_fill(const void* __restrict__ edges) {
    int e = blockIdx.x * blockDim.x + threadIdx.x;
    if (e >= NEDG) return;
    int s, d;
    if (e < EE) {
        if (g_is64) {
            s = (int)((const long long*)edges)[e];
            d = (int)((const long long*)edges)[EE + e];
        } else {
            s = ((const int*)edges)[e];
            d = ((const int*)edges)[EE + e];
        }
    } else {
        s = d = e - EE;   // self loop
    }
    int pos = atomicAdd(&g_cursor[d], 1);
    __half2 hw = __float2half2_rn(g_dinv[s] * g_dinv[d]);
    g_edge[pos] = make_int2(s << 6, *(int*)&hw);
}

// ---------------- 4) per-row sort by col (smem, deterministic order) -----
// grid 16, block 128; each block sorts rows of 125 nodes inside shared mem.
__global__ void k_sort() {
    __shared__ int2 se[SORT_BUF];
    int n0 = blockIdx.x * 125, n1 = n0 + 125;
    int b0 = g_row[n0], b1 = g_row[n1];
    int cnt = b1 - b0;
    if (cnt <= SORT_BUF) {
        for (int i = threadIdx.x; i < cnt; i += 128) se[i] = g_edge[b0 + i];
        __syncthreads();
        for (int n = n0 + threadIdx.x; n < n1; n += 128) {
            int r0 = g_row[n] - b0, r1 = g_row[n + 1] - b0;
            for (int i = r0 + 1; i < r1; i++) {
                int2 key = se[i];
                int j = i - 1;
                while (j >= r0 && se[j].x > key.x) { se[j + 1] = se[j]; j--; }
                se[j + 1] = key;
            }
        }
        __syncthreads();
        for (int i = threadIdx.x; i < cnt; i += 128) g_edge[b0 + i] = se[i];
    } else {   // fallback (never expected): global insertion sort
        for (int n = n0 + threadIdx.x; n < n1; n += 128) {
            int r0 = g_row[n], r1 = g_row[n + 1];
            for (int i = r0 + 1; i < r1; i++) {
                int2 key = g_edge[i];
                int j = i - 1;
                while (j >= r0 && g_edge[j].x > key.x) { g_edge[j + 1] = g_edge[j]; j--; }
                g_edge[j + 1] = key;
            }
        }
    }
}

// ---------------- 5) fused aggregate(HFMA2) + GEMM(tensor core) ----------
// Block per dst node, 256 threads.
// Stage A: gather fp16, accumulate fp16 (HFMA2), write sagg[64 bt][64 k].
// Stage B: 64x64x64 fp16 MMA vs smem W, fp32 accum, +bias, SiLU, fp16 out.
__global__ void k_aggemm(const float* __restrict__ W,
                         const float* __restrict__ bias, int dir) {
    __shared__ __align__(16) __half sagg[64][72];   // padded: conflict-free ldmatrix
    __shared__ __align__(16) __half Wsh[64][72];
    __shared__ float bs[64];
    __shared__ int2 sedge[MAXDEG];

    const __half* __restrict__ in  = dir ? g_h1 : g_h0;
    __half* __restrict__       out = dir ? g_h0 : g_h1;

    int n = blockIdx.x;
    int r0 = g_row[n];
    int deg = g_row[n + 1] - r0;
    int m = (deg < MAXDEG) ? deg : MAXDEG;
    int tid = threadIdx.x;

    for (int idx = tid; idx < 4096; idx += 256)
        Wsh[idx >> 6][idx & 63] = __float2half(W[idx]);
    if (tid < 64) bs[tid] = bias[tid];
    for (int j = tid; j < m; j += 256) sedge[j] = g_edge[r0 + j];
    __syncthreads();

    // ---- Stage A: aggregation ----
    int grp   = tid >> 3;          // slice 0..31 (also handles slice grp+32)
    int lane8 = (tid & 7) << 3;    // 8 halfs per thread
    const __half* p0 = in + grp * NDP + lane8;
    const __half* p1 = in + (grp + 32) * NDP + lane8;

    __half2 z = __float2half2_rn(0.0f);
    __half2 a0 = z, a1 = z, a2 = z, a3 = z;
    __half2 b0 = z, b1 = z, b2 = z, b3 = z;

    #pragma unroll 4
    for (int j = 0; j < m; j++) {
        int2 e = sedge[j];
        __half2 hw = asH2((unsigned)e.y);
        uint4 v0 = *(const uint4*)(p0 + e.x);
        uint4 v1 = *(const uint4*)(p1 + e.x);
        a0 = __hfma2(hw, asH2(v0.x), a0);
        a1 = __hfma2(hw, asH2(v0.y), a1);
        a2 = __hfma2(hw, asH2(v0.z), a2);
        a3 = __hfma2(hw, asH2(v0.w), a3);
        b0 = __hfma2(hw, asH2(v1.x), b0);
        b1 = __hfma2(hw, asH2(v1.y), b1);
        b2 = __hfma2(hw, asH2(v1.z), b2);
        b3 = __hfma2(hw, asH2(v1.w), b3);
    }
    for (int j = MAXDEG; j < deg; j++) {   // overflow fallback (never expected)
        int2 e = g_edge[r0 + j];
        __half2 hw = asH2((unsigned)e.y);
        uint4 v0 = *(const uint4*)(p0 + e.x);
        uint4 v1 = *(const uint4*)(p1 + e.x);
        a0 = __hfma2(hw, asH2(v0.x), a0);
        a1 = __hfma2(hw, asH2(v0.y), a1);
        a2 = __hfma2(hw, asH2(v0.z), a2);
        a3 = __hfma2(hw, asH2(v0.w), a3);
        b0 = __hfma2(hw, asH2(v1.x), b0);
        b1 = __hfma2(hw, asH2(v1.y), b1);
        b2 = __hfma2(hw, asH2(v1.z), b2);
        b3 = __hfma2(hw, asH2(v1.w), b3);
    }
    {
        uint4 s0, s1;
        s0.x = *(unsigned*)&a0; s0.y = *(unsigned*)&a1;
        s0.z = *(unsigned*)&a2; s0.w = *(unsigned*)&a3;
        s1.x = *(unsigned*)&b0; s1.y = *(unsigned*)&b1;
        s1.z = *(unsigned*)&b2; s1.w = *(unsigned*)&b3;
        *(uint4*)&sagg[grp     ][lane8] = s0;
        *(uint4*)&sagg[grp + 32][lane8] = s1;
    }
    __syncthreads();

    // ---- Stage B: tensor-core GEMM ----
    int w    = tid >> 5;
    int lane = tid & 31;
    int mrow0 = (w & 3) << 4;    // 16-row slab of bt slices
    int ncol0 = (w >> 2) << 5;   // 32-col slab of outputs

    float c[4][4];
    #pragma unroll
    for (int i = 0; i < 4; i++)
        #pragma unroll
        for (int j = 0; j < 4; j++) c[i][j] = 0.0f;

    #pragma unroll
    for (int kc = 0; kc < 4; kc++) {
        unsigned ra0, ra1, ra2, ra3;
        {
            unsigned aaddr = (unsigned)__cvta_generic_to_shared(
                &sagg[mrow0 + (lane & 15)][(kc << 4) + ((lane >> 4) << 3)]);
            asm volatile("ldmatrix.sync.aligned.m8n8.x4.shared.b16 {%0,%1,%2,%3}, [%4];"
                         : "=r"(ra0), "=r"(ra1), "=r"(ra2), "=r"(ra3) : "r"(aaddr));
        }
        #pragma unroll
        for (int nt = 0; nt < 4; nt++) {
            unsigned rb0, rb1;
            unsigned baddr = (unsigned)__cvta_generic_to_shared(
                &Wsh[(kc << 4) + (lane & 15)][ncol0 + (nt << 3)]);
            asm volatile("ldmatrix.sync.aligned.m8n8.x2.trans.shared.b16 {%0,%1}, [%2];"
                         : "=r"(rb0), "=r"(rb1) : "r"(baddr));
            asm volatile(
                "mma.sync.aligned.m16n8k16.row.col.f32.f16.f16.f32 "
                "{%0,%1,%2,%3}, {%4,%5,%6,%7}, {%8,%9}, {%0,%1,%2,%3};"
                : "+f"(c[nt][0]), "+f"(c[nt][1]), "+f"(c[nt][2]), "+f"(c[nt][3])
                : "r"(ra0), "r"(ra1), "r"(ra2), "r"(ra3), "r"(rb0), "r"(rb1));
        }
    }

    // epilogue: bias + SiLU + fp16 stores
    int g  = lane >> 2;
    int tg = lane & 3;
    int obase = (n << 6);
    __half* orow0 = out + (mrow0 + g) * NDP + obase;
    __half* orow1 = out + (mrow0 + g + 8) * NDP + obase;
    #pragma unroll
    for (int nt = 0; nt < 4; nt++) {
        int col = ncol0 + (nt << 3) + (tg << 1);
        float bx = bs[col], by = bs[col + 1];
        __half2 h0 = __floats2half2_rn(fsilu(c[nt][0] + bx), fsilu(c[nt][1] + by));
        __half2 h1 = __floats2half2_rn(fsilu(c[nt][2] + bx), fsilu(c[nt][3] + by));
        *(__half2*)(orow0 + col) = h0;
        *(__half2*)(orow1 + col) = h1;
    }
}

// ---------------- 6) mean pool over nodes (reads g_h1, fp16) -------------
__global__ void k_pool() {
    __shared__ float2 sp[16][32];
    int bt = blockIdx.x;
    int d2 = threadIdx.x & 31;
    int part = threadIdx.x >> 5;   // 16 partials
    const __half2* bp = (const __half2*)(g_h1 + bt * NDP) + d2;
    float2 a = make_float2(0.f, 0.f);
    for (int n0 = part; n0 < NN; n0 += 16) {
        float2 v = __half22float2(bp[n0 * 32]);
        a.x += v.x;
        a.y += v.y;
    }
    sp[part][d2] = a;
    __syncthreads();
    if (part == 0) {
        float2 t = sp[0][d2];
        #pragma unroll
        for (int i = 1; i < 16; i++) {
            float2 v = sp[i][d2];
            t.x += v.x;
            t.y += v.y;
        }
        g_pooled[bt * 64 + 2 * d2]     = t.x * (1.0f / NN);
        g_pooled[bt * 64 + 2 * d2 + 1] = t.y * (1.0f / NN);
    }
}

// ---------------- 7) LSTM (T=16, batch 4) + MLP head, single block -------
__global__ void k_lstm(const float* __restrict__ Wih, const float* __restrict__ Whh,
                       const float* __restrict__ bih, const float* __restrict__ bhh,
                       const float* __restrict__ Wp1, const float* __restrict__ bp1,
                       const float* __restrict__ Wp2, const float* __restrict__ bp2,
                       const float* __restrict__ Wp3, const float* __restrict__ bp3,
                       float* __restrict__ out) {
    __shared__ float sh[NB][DD], sc[NB][DD], sxt[NB][DD];
    __shared__ float sg[NB][4 * DD];
    __shared__ float sz1[NB][2 * DD], sz2[NB][DD];
    int tid = threadIdx.x;
    {
        int b = tid >> 6, d = tid & 63;
        sh[b][d] = 0.f;
        sc[b][d] = 0.f;
    }
    float wi[64], wh[64];
    #pragma unroll
    for (int k = 0; k < 64; k++) {
        wi[k] = Wih[tid * 64 + k];
        wh[k] = Whh[tid * 64 + k];
    }
    float bb = bih[tid] + bhh[tid];
    __syncthreads();

    for (int t = 0; t < NT; t++) {
        {
            int b = tid >> 6, d = tid & 63;
            sxt[b][d] = g_pooled[(b * NT + t) * 64 + d];
        }
        __syncthreads();
        float a0 = bb, a1 = bb, a2 = bb, a3 = bb;
        #pragma unroll
        for (int k = 0; k < 64; k++) {
            float w1 = wi[k], w2 = wh[k];
            a0 += sxt[0][k] * w1 + sh[0][k] * w2;
            a1 += sxt[1][k] * w1 + sh[1][k] * w2;
            a2 += sxt[2][k] * w1 + sh[2][k] * w2;
            a3 += sxt[3][k] * w1 + sh[3][k] * w2;
        }
        sg[0][tid] = a0; sg[1][tid] = a1; sg[2][tid] = a2; sg[3][tid] = a3;
        __syncthreads();
        {
            int b = tid >> 6, d = tid & 63;
            float ig = 1.f / (1.f + expf(-sg[b][d]));
            float fg = 1.f / (1.f + expf(-sg[b][64 + d]));
            float gg = tanhf(sg[b][128 + d]);
            float og = 1.f / (1.f + expf(-sg[b][192 + d]));
            float c = fg * sc[b][d] + ig * gg;
            sc[b][d] = c;
            sh[b][d] = og * tanhf(c);
        }
        __syncthreads();
    }

    for (int jj = tid; jj < NB * 128; jj += 256) {
        int b = jj >> 7, j = jj & 127;
        float acc = bp1[j];
        #pragma unroll
        for (int k = 0; k < 64; k++) acc += sh[b][k] * Wp1[k * 128 + j];
        sz1[b][j] = acc / (1.f + expf(-acc));
    }
    __syncthreads();
    {
        int b = tid >> 6, j2 = tid & 63;
        float acc = bp2[j2];
        #pragma unroll
        for (int j = 0; j < 128; j++) acc += sz1[b][j] * Wp2[j * 64 + j2];
        sz2[b][j2] = acc / (1.f + expf(-acc));
    }
    __syncthreads();
    if (tid < 32) {
        int b = tid >> 3, o = tid & 7;
        float acc = bp3[o];
        #pragma unroll
        for (int j2 = 0; j2 < 64; j2++) acc += sz2[b][j2] * Wp3[j2 * 8 + o];
        out[b * 8 + o] = acc;
    }
}

// ---------------- launch --------------------------------------------------
extern "C" void kernel_launch(void* const* d_in, const int* in_sizes, int n_in,
                              void* d_out, int out_size) {
    const float* x   = (const float*)d_in[0];
    const void*  ei  = d_in[1];
    const float* W1  = (const float*)d_in[2];
    const float* b1  = (const float*)d_in[3];
    const float* W2  = (const float*)d_in[4];
    const float* b2  = (const float*)d_in[5];
    const float* W3  = (const float*)d_in[6];
    const float* b3  = (const float*)d_in[7];
    const float* Wih = (const float*)d_in[8];
    const float* Whh = (const float*)d_in[9];
    const float* bih = (const float*)d_in[10];
    const float* bhh = (const float*)d_in[11];
    const float* Wp1 = (const float*)d_in[12];
    const float* bp1 = (const float*)d_in[13];
    const float* Wp2 = (const float*)d_in[14];
    const float* bp2 = (const float*)d_in[15];
    const float* Wp3 = (const float*)d_in[16];
    const float* bp3 = (const float*)d_in[17];
    float* out = (float*)d_out;

    k_detect<<<1, 32>>>((const int*)ei);
    k_cvt<<<TOT / 4 / 256, 256>>>(x);
    k_deg<<<(EE + 255) / 256, 256>>>(ei);
    k_scan<<<1, 256>>>();
    k_fill<<<(NEDG + 255) / 256, 256>>>(ei);
    k_sort<<<16, 128>>>();

    k_aggemm<<<NN, 256>>>(W1, b1, 0);   // h0 -> h1
    k_aggemm<<<NN, 256>>>(W2, b2, 1);   // h1 -> h0
    k_aggemm<<<NN, 256>>>(W3, b3, 0);   // h0 -> h1

    k_pool<<<BTB, 512>>>();
    k_lstm<<<1, 256>>>(Wih, Whh, bih, bhh, Wp1, bp1, Wp2, bp2, Wp3, bp3, out);
}

// round 4
// speedup vs baseline: 2.1506x; 1.0914x over previous
#include <cuda_runtime.h>
#include <cuda_fp16.h>

// Problem constants
#define NB   4
#define NT   16
#define BTB  64            // NB*NT
#define NN   2000
#define DD   64
#define EE   32000
#define NEDG (EE + NN)     // edges + self loops = 34000
#define NDP  (NN * DD)     // elements per (b,t) slice
#define TOT  (BTB * NDP)   // 8,192,000 elements per activation buffer
#define PBLK 148           // prep blocks: one per SM, guaranteed co-resident
#define NPB  14            // nodes per prep block for sort (148*14 >= 2000)
#define SORTBUF 2048

// ---------------- device scratch (no allocations allowed) ----------------
__device__ __half g_h0[TOT];           // 16.4 MB ping
__device__ __half g_h1[TOT];           // 16.4 MB pong
__device__ __half g_Wh[3 * 4096];      // fp16 GCN weights
__device__ int    g_row[NN + 1];
__device__ int2   g_edge[NEDG];        // (col<<6, half2(w,w) bits), row-sorted
__device__ int    g_degi[NN];          // zero-init; scan resets each launch
__device__ float  g_dinv[NN];
__device__ int    g_cursor[NN];
__device__ float  g_pooled[BTB * DD];
__device__ unsigned g_cnt;             // barrier arrivals (returns to 0)
__device__ unsigned g_gen;             // barrier generation (monotonic)

__device__ __forceinline__ float fsilu(float x) {
    return x / (1.0f + __expf(-x));
}
__device__ __forceinline__ __half2 asH2(unsigned u) { return *(__half2*)&u; }

// software grid barrier (all PBLK blocks resident: 1 per SM)
__device__ __forceinline__ void gridbar() {
    __syncthreads();
    if (threadIdx.x == 0) {
        __threadfence();
        unsigned g = *(volatile unsigned*)&g_gen;   // snapshot BEFORE arrive
        if (atomicAdd(&g_cnt, 1) == PBLK - 1) {
            atomicExch(&g_cnt, 0);
            __threadfence();
            atomicAdd(&g_gen, 1);
        } else {
            while (*(volatile unsigned*)&g_gen == g) {}
            __threadfence();
        }
    }
    __syncthreads();
}

// ---------------- fused preprocessing (single launch) --------------------
// Phase 1: x fp32->fp16, W fp32->fp16, dtype detect, degree histogram
// Phase 2: scan (block 0)   Phase 3: CSR fill   Phase 4: per-chunk smem sort
__global__ void __launch_bounds__(256, 1)
k_prep(const float* __restrict__ x, const void* __restrict__ edges,
       const float* __restrict__ W1, const float* __restrict__ W2,
       const float* __restrict__ W3) {
    __shared__ int s64;
    __shared__ int chunk[256];
    __shared__ int2 se[SORTBUF];

    int tid = threadIdx.x;
    int gid = blockIdx.x * 256 + tid;
    const int stride = PBLK * 256;

    // per-block dtype detect (warp 0): int64 LE => high words of ids are 0
    if (tid < 32) {
        const int* e32 = (const int*)edges;
        int any = 0;
        for (int j = tid; j < 128; j += 32) any |= e32[2 * j + 1];
        any = __reduce_or_sync(0xffffffffu, any);
        if (tid == 0) s64 = (any == 0) ? 1 : 0;
    }
    __syncthreads();
    int is64 = s64;

    // Phase 1a: convert x -> g_h0 (uint2 = 4 halfs per iter)
    for (int i = gid; i < TOT / 4; i += stride) {
        float4 v = ((const float4*)x)[i];
        __half2 h0 = __floats2half2_rn(v.x, v.y);
        __half2 h1 = __floats2half2_rn(v.z, v.w);
        uint2 o;
        o.x = *(unsigned*)&h0;
        o.y = *(unsigned*)&h1;
        ((uint2*)g_h0)[i] = o;
    }
    // Phase 1b: convert weights
    for (int i = gid; i < 3 * 4096; i += stride) {
        const float* Wsrc = (i < 4096) ? W1 : (i < 8192) ? W2 : W3;
        g_Wh[i] = __float2half(Wsrc[i & 4095]);
    }
    // Phase 1c: degree histogram over dst
    for (int e = gid; e < EE; e += stride) {
        int d = is64 ? (int)((const long long*)edges)[EE + e]
                     : ((const int*)edges)[EE + e];
        atomicAdd(&g_degi[d], 1);
    }
    gridbar();

    // Phase 2: exclusive scan (+1 self loop), dinv, cursors, reset degi
    if (blockIdx.x == 0) {
        int base = tid * 8;
        int vals[8];
        int s = 0;
        #pragma unroll
        for (int q = 0; q < 8; q++) {
            int idx = base + q;
            int v = 0;
            if (idx < NN) {
                v = g_degi[idx] + 1;
                g_degi[idx] = 0;
            }
            vals[q] = v;
            s += v;
        }
        chunk[tid] = s;
        __syncthreads();
        for (int off = 1; off < 256; off <<= 1) {
            int v = (tid >= off) ? chunk[tid - off] : 0;
            __syncthreads();
            chunk[tid] += v;
            __syncthreads();
        }
        int run = chunk[tid] - s;
        #pragma unroll
        for (int q = 0; q < 8; q++) {
            int idx = base + q;
            if (idx <= NN) g_row[idx] = run;
            if (idx < NN) {
                g_cursor[idx] = run;
                g_dinv[idx] = rsqrtf((float)vals[q]);
            }
            run += vals[q];
        }
    }
    gridbar();

    // Phase 3: fill CSR (edges + self loops), weight packed as half2
    for (int e = gid; e < NEDG; e += stride) {
        int s, d;
        if (e < EE) {
            if (is64) {
                s = (int)((const long long*)edges)[e];
                d = (int)((const long long*)edges)[EE + e];
            } else {
                s = ((const int*)edges)[e];
                d = ((const int*)edges)[EE + e];
            }
        } else {
            s = d = e - EE;   // self loop
        }
        int pos = atomicAdd(&g_cursor[d], 1);
        __half2 hw = __float2half2_rn(g_dinv[s] * g_dinv[d]);
        g_edge[pos] = make_int2(s << 6, *(int*)&hw);
    }
    gridbar();

    // Phase 4: per-row sort by col (deterministic summation order)
    int n0 = blockIdx.x * NPB;
    if (n0 < NN) {
        int n1 = n0 + NPB;
        if (n1 > NN) n1 = NN;
        int b0 = g_row[n0], b1 = g_row[n1];
        int cnt = b1 - b0;
        if (cnt <= SORTBUF) {
            for (int i = tid; i < cnt; i += 256) se[i] = g_edge[b0 + i];
            __syncthreads();
            for (int n = n0 + tid; n < n1; n += 256) {
                int r0 = g_row[n] - b0, r1 = g_row[n + 1] - b0;
                for (int i = r0 + 1; i < r1; i++) {
                    int2 key = se[i];
                    int j = i - 1;
                    while (j >= r0 && se[j].x > key.x) { se[j + 1] = se[j]; j--; }
                    se[j + 1] = key;
                }
            }
            __syncthreads();
            for (int i = tid; i < cnt; i += 256) g_edge[b0 + i] = se[i];
        } else {   // fallback (never expected)
            for (int n = n0 + tid; n < n1; n += 256) {
                int r0 = g_row[n], r1 = g_row[n + 1];
                for (int i = r0 + 1; i < r1; i++) {
                    int2 key = g_edge[i];
                    int j = i - 1;
                    while (j >= r0 && g_edge[j].x > key.x) {
                        g_edge[j + 1] = g_edge[j];
                        j--;
                    }
                    g_edge[j + 1] = key;
                }
            }
        }
    }
}

// ---------------- fused aggregate(HFMA2) + GEMM(tensor core) -------------
// Block per dst node, 256 threads. CSR edges read via warp-uniform __ldg
// (L1 broadcast); W loaded as fp16 directly. Single __syncthreads.
__global__ void k_aggemm(const float* __restrict__ bias, int layer, int dir) {
    __shared__ __align__(16) __half sagg[64][72];   // padded: conflict-free ldmatrix
    __shared__ __align__(16) __half Wsh[64][72];
    __shared__ float bs[64];

    const __half* __restrict__ in  = dir ? g_h1 : g_h0;
    __half* __restrict__       out = dir ? g_h0 : g_h1;

    int n = blockIdx.x;
    int r0 = g_row[n];
    int deg = g_row[n + 1] - r0;
    int tid = threadIdx.x;

    // W (fp16) -> smem: 16 halfs per thread, two LDG.128
    {
        const uint4* src = (const uint4*)(g_Wh + layer * 4096 + (tid << 4));
        uint4 v0 = src[0], v1 = src[1];
        int row = tid >> 2, col = (tid & 3) << 4;
        *(uint4*)&Wsh[row][col]     = v0;
        *(uint4*)&Wsh[row][col + 8] = v1;
    }
    if (tid < 64) bs[tid] = bias[tid];

    // ---- Stage A: aggregation (no sync needed before this) ----
    int grp   = tid >> 3;          // slice 0..31 (also handles slice grp+32)
    int lane8 = (tid & 7) << 3;    // 8 halfs per thread
    const __half* p0 = in + grp * NDP + lane8;
    const __half* p1 = in + (grp + 32) * NDP + lane8;
    const int2* ep = g_edge + r0;

    __half2 z = __float2half2_rn(0.0f);
    __half2 a0 = z, a1 = z, a2 = z, a3 = z;
    __half2 b0 = z, b1 = z, b2 = z, b3 = z;

    #pragma unroll 4
    for (int j = 0; j < deg; j++) {
        int2 e = __ldg(ep + j);                 // warp-uniform broadcast
        __half2 hw = asH2((unsigned)e.y);
        uint4 v0 = *(const uint4*)(p0 + e.x);
        uint4 v1 = *(const uint4*)(p1 + e.x);
        a0 = __hfma2(hw, asH2(v0.x), a0);
        a1 = __hfma2(hw, asH2(v0.y), a1);
        a2 = __hfma2(hw, asH2(v0.z), a2);
        a3 = __hfma2(hw, asH2(v0.w), a3);
        b0 = __hfma2(hw, asH2(v1.x), b0);
        b1 = __hfma2(hw, asH2(v1.y), b1);
        b2 = __hfma2(hw, asH2(v1.z), b2);
        b3 = __hfma2(hw, asH2(v1.w), b3);
    }
    {
        uint4 s0, s1;
        s0.x = *(unsigned*)&a0; s0.y = *(unsigned*)&a1;
        s0.z = *(unsigned*)&a2; s0.w = *(unsigned*)&a3;
        s1.x = *(unsigned*)&b0; s1.y = *(unsigned*)&b1;
        s1.z = *(unsigned*)&b2; s1.w = *(unsigned*)&b3;
        *(uint4*)&sagg[grp     ][lane8] = s0;
        *(uint4*)&sagg[grp + 32][lane8] = s1;
    }
    __syncthreads();   // covers Wsh, bs, sagg

    // ---- Stage B: tensor-core GEMM (64x64x64) ----
    int w    = tid >> 5;
    int lane = tid & 31;
    int mrow0 = (w & 3) << 4;    // 16-row slab of bt slices
    int ncol0 = (w >> 2) << 5;   // 32-col slab of outputs

    float c[4][4];
    #pragma unroll
    for (int i = 0; i < 4; i++)
        #pragma unroll
        for (int j = 0; j < 4; j++) c[i][j] = 0.0f;

    #pragma unroll
    for (int kc = 0; kc < 4; kc++) {
        unsigned ra0, ra1, ra2, ra3;
        {
            unsigned aaddr = (unsigned)__cvta_generic_to_shared(
                &sagg[mrow0 + (lane & 15)][(kc << 4) + ((lane >> 4) << 3)]);
            asm volatile("ldmatrix.sync.aligned.m8n8.x4.shared.b16 {%0,%1,%2,%3}, [%4];"
                         : "=r"(ra0), "=r"(ra1), "=r"(ra2), "=r"(ra3) : "r"(aaddr));
        }
        #pragma unroll
        for (int nt = 0; nt < 4; nt++) {
            unsigned rb0, rb1;
            unsigned baddr = (unsigned)__cvta_generic_to_shared(
                &Wsh[(kc << 4) + (lane & 15)][ncol0 + (nt << 3)]);
            asm volatile("ldmatrix.sync.aligned.m8n8.x2.trans.shared.b16 {%0,%1}, [%2];"
                         : "=r"(rb0), "=r"(rb1) : "r"(baddr));
            asm volatile(
                "mma.sync.aligned.m16n8k16.row.col.f32.f16.f16.f32 "
                "{%0,%1,%2,%3}, {%4,%5,%6,%7}, {%8,%9}, {%0,%1,%2,%3};"
                : "+f"(c[nt][0]), "+f"(c[nt][1]), "+f"(c[nt][2]), "+f"(c[nt][3])
                : "r"(ra0), "r"(ra1), "r"(ra2), "r"(ra3), "r"(rb0), "r"(rb1));
        }
    }

    // epilogue: bias + SiLU + fp16 stores
    int g  = lane >> 2;
    int tg = lane & 3;
    int obase = (n << 6);
    __half* orow0 = out + (mrow0 + g) * NDP + obase;
    __half* orow1 = out + (mrow0 + g + 8) * NDP + obase;
    #pragma unroll
    for (int nt = 0; nt < 4; nt++) {
        int col = ncol0 + (nt << 3) + (tg << 1);
        float bx = bs[col], by = bs[col + 1];
        __half2 h0 = __floats2half2_rn(fsilu(c[nt][0] + bx), fsilu(c[nt][1] + by));
        __half2 h1 = __floats2half2_rn(fsilu(c[nt][2] + bx), fsilu(c[nt][3] + by));
        *(__half2*)(orow0 + col) = h0;
        *(__half2*)(orow1 + col) = h1;
    }
}

// ---------------- mean pool over nodes (reads g_h1, fp16) ----------------
__global__ void k_pool() {
    __shared__ float2 sp[16][32];
    int bt = blockIdx.x;
    int d2 = threadIdx.x & 31;
    int part = threadIdx.x >> 5;   // 16 partials
    const __half2* bp = (const __half2*)(g_h1 + bt * NDP) + d2;
    float2 a = make_float2(0.f, 0.f);
    for (int n0 = part; n0 < NN; n0 += 16) {
        float2 v = __half22float2(bp[n0 * 32]);
        a.x += v.x;
        a.y += v.y;
    }
    sp[part][d2] = a;
    __syncthreads();
    if (part == 0) {
        float2 t = sp[0][d2];
        #pragma unroll
        for (int i = 1; i < 16; i++) {
            float2 v = sp[i][d2];
            t.x += v.x;
            t.y += v.y;
        }
        g_pooled[bt * 64 + 2 * d2]     = t.x * (1.0f / NN);
        g_pooled[bt * 64 + 2 * d2 + 1] = t.y * (1.0f / NN);
    }
}

// ---------------- LSTM (T=16, batch 4) + MLP head, single block ----------
__global__ void k_lstm(const float* __restrict__ Wih, const float* __restrict__ Whh,
                       const float* __restrict__ bih, const float* __restrict__ bhh,
                       const float* __restrict__ Wp1, const float* __restrict__ bp1,
                       const float* __restrict__ Wp2, const float* __restrict__ bp2,
                       const float* __restrict__ Wp3, const float* __restrict__ bp3,
                       float* __restrict__ out) {
    __shared__ float sh[NB][DD], sc[NB][DD], sxt[NB][DD];
    __shared__ float sg[NB][4 * DD];
    __shared__ float sz1[NB][2 * DD], sz2[NB][DD];
    int tid = threadIdx.x;
    {
        int b = tid >> 6, d = tid & 63;
        sh[b][d] = 0.f;
        sc[b][d] = 0.f;
    }
    float wi[64], wh[64];
    #pragma unroll
    for (int k = 0; k < 64; k++) {
        wi[k] = Wih[tid * 64 + k];
        wh[k] = Whh[tid * 64 + k];
    }
    float bb = bih[tid] + bhh[tid];
    __syncthreads();

    for (int t = 0; t < NT; t++) {
        {
            int b = tid >> 6, d = tid & 63;
            sxt[b][d] = g_pooled[(b * NT + t) * 64 + d];
        }
        __syncthreads();
        float a0 = bb, a1 = bb, a2 = bb, a3 = bb;
        #pragma unroll
        for (int k = 0; k < 64; k++) {
            float w1 = wi[k], w2 = wh[k];
            a0 += sxt[0][k] * w1 + sh[0][k] * w2;
            a1 += sxt[1][k] * w1 + sh[1][k] * w2;
            a2 += sxt[2][k] * w1 + sh[2][k] * w2;
            a3 += sxt[3][k] * w1 + sh[3][k] * w2;
        }
        sg[0][tid] = a0; sg[1][tid] = a1; sg[2][tid] = a2; sg[3][tid] = a3;
        __syncthreads();
        {
            int b = tid >> 6, d = tid & 63;
            float ig = 1.f / (1.f + expf(-sg[b][d]));
            float fg = 1.f / (1.f + expf(-sg[b][64 + d]));
            float gg = tanhf(sg[b][128 + d]);
            float og = 1.f / (1.f + expf(-sg[b][192 + d]));
            float c = fg * sc[b][d] + ig * gg;
            sc[b][d] = c;
            sh[b][d] = og * tanhf(c);
        }
        __syncthreads();
    }

    for (int jj = tid; jj < NB * 128; jj += 256) {
        int b = jj >> 7, j = jj & 127;
        float acc = bp1[j];
        #pragma unroll
        for (int k = 0; k < 64; k++) acc += sh[b][k] * Wp1[k * 128 + j];
        sz1[b][j] = acc / (1.f + expf(-acc));
    }
    __syncthreads();
    {
        int b = tid >> 6, j2 = tid & 63;
        float acc = bp2[j2];
        #pragma unroll
        for (int j = 0; j < 128; j++) acc += sz1[b][j] * Wp2[j * 64 + j2];
        sz2[b][j2] = acc / (1.f + expf(-acc));
    }
    __syncthreads();
    if (tid < 32) {
        int b = tid >> 3, o = tid & 7;
        float acc = bp3[o];
        #pragma unroll
        for (int j2 = 0; j2 < 64; j2++) acc += sz2[b][j2] * Wp3[j2 * 8 + o];
        out[b * 8 + o] = acc;
    }
}

// ---------------- launch --------------------------------------------------
extern "C" void kernel_launch(void* const* d_in, const int* in_sizes, int n_in,
                              void* d_out, int out_size) {
    const float* x   = (const float*)d_in[0];
    const void*  ei  = d_in[1];
    const float* W1  = (const float*)d_in[2];
    const float* b1  = (const float*)d_in[3];
    const float* W2  = (const float*)d_in[4];
    const float* b2  = (const float*)d_in[5];
    const float* W3  = (const float*)d_in[6];
    const float* b3  = (const float*)d_in[7];
    const float* Wih = (const float*)d_in[8];
    const float* Whh = (const float*)d_in[9];
    const float* bih = (const float*)d_in[10];
    const float* bhh = (const float*)d_in[11];
    const float* Wp1 = (const float*)d_in[12];
    const float* bp1 = (const float*)d_in[13];
    const float* Wp2 = (const float*)d_in[14];
    const float* bp2 = (const float*)d_in[15];
    const float* Wp3 = (const float*)d_in[16];
    const float* bp3 = (const float*)d_in[17];
    float* out = (float*)d_out;

    k_prep<<<PBLK, 256>>>(x, ei, W1, W2, W3);

    k_aggemm<<<NN, 256>>>(b1, 0, 0);   // h0 -> h1
    k_aggemm<<<NN, 256>>>(b2, 1, 1);   // h1 -> h0
    k_aggemm<<<NN, 256>>>(b3, 2, 0);   // h0 -> h1

    k_pool<<<BTB, 512>>>();
    k_lstm<<<1, 256>>>(Wih, Whh, bih, bhh, Wp1, bp1, Wp2, bp2, Wp3, bp3, out);
}